// round 3
// baseline (speedup 1.0000x reference)
#include <cuda_runtime.h>
#include <math.h>

#define N_NODES 512
#define DIM 128
#define NA 192          // total anchors
#define G3 384          // 3*DIM

// ---------------- scratch (no allocations allowed) ----------------
__device__ float g_x[N_NODES * DIM];
__device__ float g_abn[N_NODES];
__device__ float g_tpos[N_NODES];
__device__ float g_Gi[6 * N_NODES * G3];
__device__ float g_hout[NA * 2 * DIM];
__device__ float g_abnout[NA * 2];
__device__ float g_WihT[6 * DIM * G3];   // [sd][k][row]
__device__ float g_WhhT[6 * DIM * G3];   // [sd][k][row]
__device__ int   g_pairs[96][2];         // per (s, local pair): 2 anchor ids
__device__ int   g_order[96];            // global pair order, width desc

__device__ __forceinline__ float sigf(float x) { return 1.f / (1.f + __expf(-x)); }
__device__ __forceinline__ float tanhfast(float x) { return 2.f / (1.f + __expf(-2.f * x)) - 1.f; }

// ---------------- kernel 1: preprocess ----------------
__global__ void k_pre(const float* __restrict__ emb, const float* __restrict__ tp,
                      const float* __restrict__ pred, const float* __restrict__ al_p,
                      const float* __restrict__ kern)
{
    int tid = blockIdx.x * blockDim.x + threadIdx.x;
    if (tid < N_NODES * DIM) {
        int n = tid >> 7, d = tid & 127;
        float freq = (10.f / 127.f) * (float)d;
        g_x[tid] = emb[tid] + 0.05f * sinf(tp[n] * freq);
    }
    if (tid < N_NODES) {
        int n = tid;
        float kv[5];
        #pragma unroll
        for (int k = 0; k < 5; k++) kv[k] = kern[k];
        float sv[5];
        #pragma unroll
        for (int c = 0; c < 5; c++) {
            float acc = 0.f;
            #pragma unroll
            for (int k = 0; k < 5; k++) {
                int nn = n + k - 2;
                if (nn >= 0 && nn < N_NODES) acc += kv[k] * pred[nn * 5 + c];
            }
            sv[c] = acc;
        }
        float m = sv[0];
        #pragma unroll
        for (int c = 1; c < 5; c++) m = fmaxf(m, sv[c]);
        float den = 0.f;
        #pragma unroll
        for (int c = 0; c < 5; c++) den += __expf(sv[c] - m);
        g_abn[n] = __expf(sv[0] - m) / den;
        g_tpos[n] = tp[n] * al_p[0];
    }
}

// ---------------- kernel 1b: transpose GRU weights for coalesced loads ----------------
__global__ void k_tr(const float* __restrict__ Wih, const float* __restrict__ Whh)
{
    int o = blockIdx.x * 256 + threadIdx.x;
    const int total = 6 * DIM * G3;
    if (o >= total) return;
    int sd = o / (DIM * G3);
    int r  = o % (DIM * G3);
    int k  = r / G3;
    int row = r % G3;
    size_t src = (size_t)sd * G3 * DIM + (size_t)row * DIM + k;
    g_WihT[o] = Wih[src];
    g_WhhT[o] = Whh[src];
}

// ---------------- kernel 1c: width-sorted pairing within scale + global pair order ----------------
__global__ void k_rank(const float* __restrict__ anchors)
{
    __shared__ float wdt[NA];
    int i = threadIdx.x;   // 0..191
    float w = anchors[2 * i + 1] - anchors[2 * i];
    wdt[i] = w;
    __syncthreads();
    int s = i >> 6, base = s * 64;
    int r = 0;
    for (int j = 0; j < 64; j++) {
        float wj = wdt[base + j];
        if (wj > w || (wj == w && base + j < i)) r++;
    }
    g_pairs[s * 32 + (r >> 1)][r & 1] = i;
    __syncthreads();   // orders the gmem writes within the block too
    if (i < 96) {
        float pw = -1.f;
        // width of slot-0 anchor of pair i (the wider one)
        int a0 = g_pairs[i][0];
        pw = wdt[a0];
        int g = 0;
        for (int j = 0; j < 96; j++) {
            float pj = wdt[g_pairs[j][0]];
            if (pj > pw || (pj == pw && j < i)) g++;
        }
        g_order[g] = i;
    }
}

// ---------------- kernel 2: Gi = x @ Wih^T + bih, pipelined weight loads ----------------
__global__ __launch_bounds__(384) void k_gi(const float* __restrict__ bih)
{
    int sd = blockIdx.y;
    int tile = blockIdx.x;      // 16 nodes per tile
    int t = threadIdx.x;
    __shared__ __align__(16) float sxT[DIM][20];
    for (int i = t; i < DIM * 16; i += 384) {
        int k = i >> 4, nn = i & 15;
        sxT[k][nn] = g_x[(tile * 16 + nn) * DIM + k];
    }
    __syncthreads();

    unsigned hb;
    asm("{.reg .u64 t0; cvta.to.shared.u64 t0,%1; cvt.u32.u64 %0,t0;}" : "=r"(hb) : "l"(&sxT[0][0]));

    const float* wt = g_WihT + (size_t)sd * DIM * G3 + t;
    unsigned long long acc[8];
    #pragma unroll
    for (int j = 0; j < 8; j++) acc[j] = 0ull;

    float wcur[4], wnext[4];
    #pragma unroll
    for (int j = 0; j < 4; j++) wcur[j] = wt[(size_t)j * G3];

    for (int k0 = 0; k0 < DIM; k0 += 4) {
        if (k0 + 4 < DIM) {
            #pragma unroll
            for (int j = 0; j < 4; j++) wnext[j] = wt[(size_t)(k0 + 4 + j) * G3];
        }
        #pragma unroll
        for (int kk = 0; kk < 4; kk++) {
            unsigned long long w2;
            asm("mov.b64 %0,{%1,%1};" : "=l"(w2) : "f"(wcur[kk]));
            unsigned rowaddr = hb + (k0 + kk) * 80;
            #pragma unroll
            for (int q = 0; q < 4; q++) {
                unsigned long long h0, h1;
                asm volatile("ld.shared.v2.b64 {%0,%1},[%2];" : "=l"(h0), "=l"(h1) : "r"(rowaddr + q * 16));
                asm("fma.rn.f32x2 %0,%1,%2,%0;" : "+l"(acc[2 * q])     : "l"(w2), "l"(h0));
                asm("fma.rn.f32x2 %0,%1,%2,%0;" : "+l"(acc[2 * q + 1]) : "l"(w2), "l"(h1));
            }
        }
        #pragma unroll
        for (int j = 0; j < 4; j++) wcur[j] = wnext[j];
    }
    float b = bih[sd * G3 + t];
    #pragma unroll
    for (int j = 0; j < 8; j++) {
        float lo, hi;
        asm("mov.b64 {%0,%1},%2;" : "=f"(lo), "=f"(hi) : "l"(acc[j]));
        g_Gi[((size_t)sd * N_NODES + tile * 16 + 2 * j)     * G3 + t] = lo + b;
        g_Gi[((size_t)sd * N_NODES + tile * 16 + 2 * j + 1) * G3 + t] = hi + b;
    }
}

// ---------------- kernel 3: GRU recurrence, 2 anchors (same sd) per block ----------------
__global__ __launch_bounds__(384, 1) void k_gru(const float* __restrict__ anchors,
                                                const float* __restrict__ bhh,
                                                const float* __restrict__ aWih,
                                                const float* __restrict__ aWhh,
                                                const float* __restrict__ abih,
                                                const float* __restrict__ abhh)
{
    int t = threadIdx.x;
    __shared__ int sh_task[4];                 // aA, aB, s, dir
    __shared__ __align__(16) float hA[DIM];
    __shared__ __align__(16) float hB[DIM];
    __shared__ float ghA[G3];
    __shared__ float ghB[G3];
    __shared__ unsigned short idxA[N_NODES];
    __shared__ unsigned short idxB[N_NODES];
    __shared__ int sh_len[2];
    __shared__ float sh_abh[2];
    __shared__ float aw[12];

    if (t == 0) {
        int pr = g_order[blockIdx.x >> 1];
        sh_task[0] = g_pairs[pr][0];
        sh_task[1] = g_pairs[pr][1];
        sh_task[2] = pr >> 5;                  // scale
        sh_task[3] = blockIdx.x & 1;           // dir
    }
    __syncthreads();
    int aA = sh_task[0], aB = sh_task[1], s = sh_task[2], dir = sh_task[3];
    int sd = s * 2 + dir;

    int wid = t >> 5, lane = t & 31;
    if (wid < 2) {                             // warp0 -> A, warp1 -> B compaction
        int aa = wid ? aB : aA;
        float stt = anchors[2 * aa], enn = anchors[2 * aa + 1];
        unsigned short* idx = wid ? idxB : idxA;
        int off = 0;
        for (int base = 0; base < N_NODES; base += 32) {
            int n = base + lane;
            float tp = g_tpos[n];
            bool m = (tp >= stt) && (tp <= enn);
            unsigned bal = __ballot_sync(0xffffffffu, m);
            if (m) idx[off + __popc(bal & ((1u << lane) - 1u))] = (unsigned short)n;
            off += __popc(bal);
        }
        if (lane == 0) { sh_len[wid] = off; sh_abh[wid] = 0.f; }
    }
    if (t < DIM) { hA[t] = 0.f; hB[t] = 0.f; }
    if (t >= 64 && t < 67) {
        int j = t - 64, base = sd * 3;
        aw[j]     = aWih[base + j];
        aw[3 + j] = aWhh[base + j];
        aw[6 + j] = abih[base + j];
        aw[9 + j] = abhh[base + j];
    }

    // Whh row t into registers (coalesced, f32x2-packed)
    const float* wt = g_WhhT + (size_t)sd * DIM * G3 + t;
    unsigned long long w[64];
    #pragma unroll
    for (int k = 0; k < 64; k++) {
        float w0 = wt[(size_t)(2 * k) * G3];
        float w1 = wt[(size_t)(2 * k + 1) * G3];
        asm("mov.b64 %0,{%1,%2};" : "=l"(w[k]) : "f"(w0), "f"(w1));
    }
    float bh = bhh[sd * G3 + t];

    unsigned hbA, hbB;
    asm("{.reg .u64 t0; cvta.to.shared.u64 t0,%1; cvt.u32.u64 %0,t0;}" : "=r"(hbA) : "l"((float*)hA));
    asm("{.reg .u64 t0; cvta.to.shared.u64 t0,%1; cvt.u32.u64 %0,t0;}" : "=r"(hbB) : "l"((float*)hB));
    __syncthreads();

    int lenA = sh_len[0], lenB = sh_len[1];
    int L = lenA > lenB ? lenA : lenB;
    const float* Gi = g_Gi + (size_t)sd * N_NODES * G3;

    for (int step = 0; step < L; step++) {
        bool actA = step < lenA, actB = step < lenB;
        float gi0 = 0.f, gi1 = 0.f, gi2 = 0.f, ab_in = 0.f;
        if (t < DIM) {
            if (actA) {
                int node = dir ? (int)idxA[lenA - 1 - step] : (int)idxA[step];
                const float* gp = Gi + (size_t)node * G3;
                gi0 = gp[t]; gi1 = gp[DIM + t]; gi2 = gp[2 * DIM + t];
            }
        } else if (t < 2 * DIM) {
            if (actB) {
                int node = dir ? (int)idxB[lenB - 1 - step] : (int)idxB[step];
                int tt = t - DIM;
                const float* gp = Gi + (size_t)node * G3;
                gi0 = gp[tt]; gi1 = gp[DIM + tt]; gi2 = gp[2 * DIM + tt];
            }
        } else if (t == 256) {
            if (actA) ab_in = g_abn[dir ? (int)idxA[lenA - 1 - step] : (int)idxA[step]];
        } else if (t == 257) {
            if (actB) ab_in = g_abn[dir ? (int)idxB[lenB - 1 - step] : (int)idxB[step]];
        }

        // gh = Whh_row_t . h  for both anchors (shared weights)
        unsigned long long accA = 0, accB = 0;
        #pragma unroll
        for (int i = 0; i < 32; i++) {
            unsigned long long a0, a1;
            asm volatile("ld.shared.v2.b64 {%0,%1},[%2];" : "=l"(a0), "=l"(a1) : "r"(hbA + i * 16));
            asm("fma.rn.f32x2 %0,%1,%2,%0;" : "+l"(accA) : "l"(w[2 * i])     , "l"(a0));
            asm("fma.rn.f32x2 %0,%1,%2,%0;" : "+l"(accA) : "l"(w[2 * i + 1]) , "l"(a1));
            unsigned long long b0, b1;
            asm volatile("ld.shared.v2.b64 {%0,%1},[%2];" : "=l"(b0), "=l"(b1) : "r"(hbB + i * 16));
            asm("fma.rn.f32x2 %0,%1,%2,%0;" : "+l"(accB) : "l"(w[2 * i])     , "l"(b0));
            asm("fma.rn.f32x2 %0,%1,%2,%0;" : "+l"(accB) : "l"(w[2 * i + 1]) , "l"(b1));
        }
        float pa0, pa1, pb0, pb1;
        asm("mov.b64 {%0,%1},%2;" : "=f"(pa0), "=f"(pa1) : "l"(accA));
        asm("mov.b64 {%0,%1},%2;" : "=f"(pb0), "=f"(pb1) : "l"(accB));
        ghA[t] = bh + pa0 + pa1;
        ghB[t] = bh + pb0 + pb1;
        __syncthreads();

        if (t < DIM) {
            if (actA) {
                float r  = sigf(gi0 + ghA[t]);
                float z  = sigf(gi1 + ghA[DIM + t]);
                float nn = tanhfast(gi2 + r * ghA[2 * DIM + t]);
                hA[t] = (1.f - z) * nn + z * hA[t];
            }
        } else if (t < 2 * DIM) {
            if (actB) {
                int tt = t - DIM;
                float r  = sigf(gi0 + ghB[tt]);
                float z  = sigf(gi1 + ghB[DIM + tt]);
                float nn = tanhfast(gi2 + r * ghB[2 * DIM + tt]);
                hB[tt] = (1.f - z) * nn + z * hB[tt];
            }
        } else if (t == 256) {
            if (actA) {
                float h = sh_abh[0];
                float r  = sigf(aw[0] * ab_in + aw[6] + aw[3] * h + aw[9]);
                float z  = sigf(aw[1] * ab_in + aw[7] + aw[4] * h + aw[10]);
                float nn = tanhfast(aw[2] * ab_in + aw[8] + r * (aw[5] * h + aw[11]));
                sh_abh[0] = (1.f - z) * nn + z * h;
            }
        } else if (t == 257) {
            if (actB) {
                float h = sh_abh[1];
                float r  = sigf(aw[0] * ab_in + aw[6] + aw[3] * h + aw[9]);
                float z  = sigf(aw[1] * ab_in + aw[7] + aw[4] * h + aw[10]);
                float nn = tanhfast(aw[2] * ab_in + aw[8] + r * (aw[5] * h + aw[11]));
                sh_abh[1] = (1.f - z) * nn + z * h;
            }
        }
        __syncthreads();
    }

    if (t < DIM)      g_hout[((size_t)aA * 2 + dir) * DIM + t] = hA[t];
    else if (t < 256) g_hout[((size_t)aB * 2 + dir) * DIM + (t - DIM)] = hB[t - DIM];
    else if (t == 256) g_abnout[aA * 2 + dir] = sh_abh[0];
    else if (t == 257) g_abnout[aB * 2 + dir] = sh_abh[1];
}

// ---------------- kernel 4: per-anchor MLP head, 8-way ILP ----------------
__global__ __launch_bounds__(256) void k_head(const float* __restrict__ anchors,
                                              const float* __restrict__ al_p,
                                              const float* __restrict__ W1, const float* __restrict__ b1,
                                              const float* __restrict__ W2, const float* __restrict__ b2,
                                              const float* __restrict__ W3, const float* __restrict__ b3,
                                              const float* __restrict__ start_w,
                                              const float* __restrict__ end_w,
                                              float* __restrict__ out)
{
    int a = blockIdx.x;
    int s = a >> 6;
    int t = threadIdx.x;
    const int FIN = 2 * DIM + 3;   // 259
    const int FOUT = 47;

    __shared__ float sf[FIN + 1];
    __shared__ float h1[256];
    __shared__ float h2[256];
    __shared__ float o[FOUT];
    __shared__ float soeo[2];

    float al = al_p[0];
    if (t < DIM) {
        sf[t]       = g_hout[((size_t)a * 2 + 0) * DIM + t];
        sf[DIM + t] = g_hout[((size_t)a * 2 + 1) * DIM + t];
    }
    if (t == 0) {
        sf[256] = 0.5f * (g_abnout[a * 2] + g_abnout[a * 2 + 1]);
        float stt = anchors[a * 2], enn = anchors[a * 2 + 1];
        sf[257] = (stt + enn) * 0.5f / al;
        sf[258] = (enn - stt) / al;
    }
    __syncthreads();

    {
        const float* W = W1 + (size_t)s * FIN * 256 + t;
        float acc[8];
        #pragma unroll
        for (int j = 0; j < 8; j++) acc[j] = 0.f;
        for (int i = 0; i < 256; i += 8) {
            #pragma unroll
            for (int j = 0; j < 8; j++) acc[j] += W[(size_t)(i + j) * 256] * sf[i + j];
        }
        acc[0] += W[(size_t)256 * 256] * sf[256];
        acc[1] += W[(size_t)257 * 256] * sf[257];
        acc[2] += W[(size_t)258 * 256] * sf[258];
        float r = (((acc[0] + acc[1]) + (acc[2] + acc[3])) + ((acc[4] + acc[5]) + (acc[6] + acc[7])))
                  + b1[s * 256 + t];
        h1[t] = fmaxf(r, 0.f);
    }
    __syncthreads();

    {
        const float* W = W2 + (size_t)s * 256 * 256 + t;
        float acc[8];
        #pragma unroll
        for (int j = 0; j < 8; j++) acc[j] = 0.f;
        for (int i = 0; i < 256; i += 8) {
            #pragma unroll
            for (int j = 0; j < 8; j++) acc[j] += W[(size_t)(i + j) * 256] * h1[i + j];
        }
        float r = (((acc[0] + acc[1]) + (acc[2] + acc[3])) + ((acc[4] + acc[5]) + (acc[6] + acc[7])))
                  + b2[s * 256 + t];
        h2[t] = fmaxf(r, 0.f);
    }
    __syncthreads();

    if (t < FOUT) {
        const float* W = W3 + (size_t)s * 256 * FOUT + t;
        float acc[8];
        #pragma unroll
        for (int j = 0; j < 8; j++) acc[j] = 0.f;
        for (int i = 0; i < 256; i += 8) {
            #pragma unroll
            for (int j = 0; j < 8; j++) acc[j] += W[(size_t)(i + j) * FOUT] * h2[i + j];
        }
        o[t] = (((acc[0] + acc[1]) + (acc[2] + acc[3])) + ((acc[4] + acc[5]) + (acc[6] + acc[7])))
               + b3[s * FOUT + t];
    }
    __syncthreads();

    if (t < 2) {
        const float* wv = (t == 0) ? (start_w + s * 21) : (end_w + s * 21);
        const float* ov = o + t * 21;
        float m = -1e30f;
        for (int j = 0; j < 21; j++) m = fmaxf(m, ov[j]);
        float den = 0.f, num = 0.f;
        for (int j = 0; j < 21; j++) { float e = __expf(ov[j] - m); den += e; num += e * wv[j]; }
        soeo[t] = num / den;
    }
    __syncthreads();

    if (t == 0) {
        float stt = anchors[a * 2], enn = anchors[a * 2 + 1];
        out[a * 2]      = fminf(fmaxf(stt + soeo[0], 0.f), al);
        out[a * 2 + 1]  = fminf(fmaxf(enn + soeo[1], 0.f), al);
        out[2 * NA + a] = o[42];
    }
    if (t < 4) out[3 * NA + a * 4 + t] = o[43 + t];
}

// ---------------- launcher ----------------
extern "C" void kernel_launch(void* const* d_in, const int* in_sizes, int n_in,
                              void* d_out, int out_size)
{
    const float* emb   = (const float*)d_in[0];
    const float* tp    = (const float*)d_in[1];
    const float* pred  = (const float*)d_in[2];
    const float* al_p  = (const float*)d_in[3];
    const float* anc   = (const float*)d_in[4];
    const float* kern  = (const float*)d_in[5];
    const float* fWih  = (const float*)d_in[6];
    const float* fWhh  = (const float*)d_in[7];
    const float* fbih  = (const float*)d_in[8];
    const float* fbhh  = (const float*)d_in[9];
    const float* aWih  = (const float*)d_in[10];
    const float* aWhh  = (const float*)d_in[11];
    const float* abih  = (const float*)d_in[12];
    const float* abhh  = (const float*)d_in[13];
    const float* sw    = (const float*)d_in[14];
    const float* ew    = (const float*)d_in[15];
    const float* W1    = (const float*)d_in[16];
    const float* b1    = (const float*)d_in[17];
    const float* W2    = (const float*)d_in[18];
    const float* b2    = (const float*)d_in[19];
    const float* W3    = (const float*)d_in[20];
    const float* b3    = (const float*)d_in[21];
    float* outp = (float*)d_out;

    k_pre<<<(N_NODES * DIM + 255) / 256, 256>>>(emb, tp, pred, al_p, kern);
    k_tr<<<(6 * DIM * G3 + 255) / 256, 256>>>(fWih, fWhh);
    k_rank<<<1, NA>>>(anc);
    k_gi<<<dim3(N_NODES / 16, 6), 384>>>(fbih);
    k_gru<<<NA, 384>>>(anc, fbhh, aWih, aWhh, abih, abhh);
    k_head<<<NA, 256>>>(anc, al_p, W1, b1, W2, b2, W3, b3, sw, ew, outp);
}